// round 4
// baseline (speedup 1.0000x reference)
#include <cuda_runtime.h>

// ---------------------------------------------------------------------------
// MogrifierRNN: S=512 steps, B=128, M=N=512, K=256, NQ=2 mogrify pairs.
//
// Persistent-kernel design: one kernel runs the whole sequence; grid-wide
// barriers separate the 5 dependent matmul phases per timestep.
//   P1: xx = 2*sig(h @ Q0^T) * x[t]
//   P2: h  = 2*sig(xx @ R0^T) * h
//   P3: xx = 2*sig(h @ Q1^T) * xx
//   P4: h  = 2*sig(xx @ R1^T) * h
//   P5: gates = xx@Wih^T + h@Whh^T + b ; LSTM pointwise ; write out[t], h', c
// ---------------------------------------------------------------------------

#define S_LEN 512
#define B_DIM 128
#define HID   512      // M == N == 512
#define K_RANK 256
#define NQP   2

#define GRID_BLOCKS 128
#define NT          256
#define CHUNK       128
#define PITCH       33     // smem pitch: stride-33 => conflict-free both ways

// ------------------------- device scratch (no allocs allowed) --------------
__device__ float g_Q[NQP * HID * HID];   // Q[i][m][n], row m contiguous
__device__ float g_R[NQP * HID * HID];   // R[i][n][m], row n contiguous
__device__ float g_xx[B_DIM * HID];
__device__ float g_h[2][B_DIM * HID];    // double-buffered hidden state
__device__ float g_c[B_DIM * HID];
__device__ unsigned int g_bar;

__global__ void mg_init() { g_bar = 0u; }

__device__ __forceinline__ float sigf(float v) {
    return 1.0f / (1.0f + __expf(-v));
}

// Grid barrier: release (fence+atomic arrive) / acquire (spin + fence; the
// gpu-scope fence emits CCTL.IVALL on sm_103a, flushing stale L1D lines of
// cross-block activation data).
__device__ __forceinline__ void grid_barrier(unsigned int& epoch) {
    epoch += GRID_BLOCKS;
    __threadfence();
    __syncthreads();
    if (threadIdx.x == 0) {
        atomicAdd(&g_bar, 1u);
        while (*((volatile unsigned int*)&g_bar) < epoch) { }
    }
    __syncthreads();
    __threadfence();
}

// Stage A rows [r0, r0+32) x cols [kc, kc+128) transposed into smem:
// As[k*PITCH + row]. Global read coalesced (lanes = consecutive k);
// smem store banks (33k+row)%32 = (k+row)%32 -> conflict-free.
__device__ __forceinline__ void load_chunk(float* As, const float* A,
                                           int r0, int kc) {
#pragma unroll
    for (int i = 0; i < 16; i++) {
        int e   = i * NT + (int)threadIdx.x;
        int row = e >> 7;
        int k   = e & (CHUNK - 1);
        As[k * PITCH + row] = A[(r0 + row) * HID + kc + k];
    }
}

// One mogrifier matmul phase: Out[b,j] = 2*sig( sum_k A[b,k]*W[j,k] ) * Mul[b,j]
// Tile [32 rows x 16 cols] per block (128 tiles). Thread: 1 row, 2 cols.
__device__ __noinline__ void mog_phase(float* As, const float* A,
                                       const float* W, const float* Mul,
                                       float* Out) {
    const int rt = blockIdx.x & 3, ct = (int)blockIdx.x >> 2;
    const int r0 = rt * 32, j0 = ct * 16;
    const int lane = threadIdx.x & 31, wp = (int)threadIdx.x >> 5;
    const int jA = j0 + 2 * wp, jB = jA + 1;
    float acc0 = 0.f, acc1 = 0.f;
    const float* WA = W + jA * HID;
    const float* WB = W + jB * HID;

    for (int kc = 0; kc < HID; kc += CHUNK) {
        load_chunk(As, A, r0, kc);
        __syncthreads();
#pragma unroll
        for (int k = 0; k < CHUNK; k += 4) {
            float4 w0 = *reinterpret_cast<const float4*>(WA + kc + k);
            float4 w1 = *reinterpret_cast<const float4*>(WB + kc + k);
            float a0 = As[(k + 0) * PITCH + lane];
            float a1 = As[(k + 1) * PITCH + lane];
            float a2 = As[(k + 2) * PITCH + lane];
            float a3 = As[(k + 3) * PITCH + lane];
            acc0 = fmaf(a0, w0.x, acc0); acc0 = fmaf(a1, w0.y, acc0);
            acc0 = fmaf(a2, w0.z, acc0); acc0 = fmaf(a3, w0.w, acc0);
            acc1 = fmaf(a0, w1.x, acc1); acc1 = fmaf(a1, w1.y, acc1);
            acc1 = fmaf(a2, w1.z, acc1); acc1 = fmaf(a3, w1.w, acc1);
        }
        __syncthreads();
    }
    const int b = r0 + lane;
    float m0 = Mul[b * HID + jA];
    float m1 = Mul[b * HID + jB];
    Out[b * HID + jA] = 2.0f * sigf(acc0) * m0;
    Out[b * HID + jB] = 2.0f * sigf(acc1) * m1;
}

__device__ __forceinline__ void lstm_out(float ai, float af, float ag, float ao,
                                         int b, int j,
                                         const float* bih, const float* bhh,
                                         float* hn, float* outp, float* tail,
                                         int t) {
    float ig = ai + bih[j]        + bhh[j];
    float fg = af + bih[512 + j]  + bhh[512 + j];
    float gg = ag + bih[1024 + j] + bhh[1024 + j];
    float og = ao + bih[1536 + j] + bhh[1536 + j];
    int idx = b * HID + j;
    float c_new = sigf(fg) * g_c[idx] + sigf(ig) * tanhf(gg);
    float h_new = sigf(og) * tanhf(c_new);
    g_c[idx]  = c_new;
    hn[idx]   = h_new;
    outp[idx] = h_new;
    if (t == S_LEN - 1) {               // final (h, c) tail of the output
        tail[idx]                = h_new;
        tail[B_DIM * HID + idx]  = c_new;
    }
}

// Gates phase: for (b,n) compute the 4 gate dots over xx (Wih) then h (Whh),
// then LSTM pointwise. Tile [32 rows x 16 n-cols]; thread: 1 row, 2 n-cols,
// 8 accumulators.
__device__ __forceinline__ void gates_phase(float* As, const float* xx,
                                            const float* h,
                                            const float* Wih, const float* Whh,
                                            const float* bih, const float* bhh,
                                            float* hn, float* outp, float* tail,
                                            int t) {
    const int rt = blockIdx.x & 3, ct = (int)blockIdx.x >> 2;
    const int r0 = rt * 32, j0 = ct * 16;
    const int lane = threadIdx.x & 31, wp = (int)threadIdx.x >> 5;
    const int jA = j0 + 2 * wp, jB = jA + 1;
    float accA0 = 0.f, accA1 = 0.f, accA2 = 0.f, accA3 = 0.f;
    float accB0 = 0.f, accB1 = 0.f, accB2 = 0.f, accB3 = 0.f;

#pragma unroll 1
    for (int src = 0; src < 2; src++) {
        const float* A = src ? h : xx;
        const float* W = src ? Whh : Wih;
        const float* W0A = W + (0 * HID + jA) * HID;
        const float* W1A = W + (1 * HID + jA) * HID;
        const float* W2A = W + (2 * HID + jA) * HID;
        const float* W3A = W + (3 * HID + jA) * HID;
        const float* W0B = W + (0 * HID + jB) * HID;
        const float* W1B = W + (1 * HID + jB) * HID;
        const float* W2B = W + (2 * HID + jB) * HID;
        const float* W3B = W + (3 * HID + jB) * HID;
#pragma unroll 1
        for (int kc = 0; kc < HID; kc += CHUNK) {
            load_chunk(As, A, r0, kc);
            __syncthreads();
#pragma unroll 4
            for (int k = 0; k < CHUNK; k += 4) {
                float a0 = As[(k + 0) * PITCH + lane];
                float a1 = As[(k + 1) * PITCH + lane];
                float a2 = As[(k + 2) * PITCH + lane];
                float a3 = As[(k + 3) * PITCH + lane];
                float4 w;
                w = *reinterpret_cast<const float4*>(W0A + kc + k);
                accA0 = fmaf(a0, w.x, accA0); accA0 = fmaf(a1, w.y, accA0);
                accA0 = fmaf(a2, w.z, accA0); accA0 = fmaf(a3, w.w, accA0);
                w = *reinterpret_cast<const float4*>(W1A + kc + k);
                accA1 = fmaf(a0, w.x, accA1); accA1 = fmaf(a1, w.y, accA1);
                accA1 = fmaf(a2, w.z, accA1); accA1 = fmaf(a3, w.w, accA1);
                w = *reinterpret_cast<const float4*>(W2A + kc + k);
                accA2 = fmaf(a0, w.x, accA2); accA2 = fmaf(a1, w.y, accA2);
                accA2 = fmaf(a2, w.z, accA2); accA2 = fmaf(a3, w.w, accA2);
                w = *reinterpret_cast<const float4*>(W3A + kc + k);
                accA3 = fmaf(a0, w.x, accA3); accA3 = fmaf(a1, w.y, accA3);
                accA3 = fmaf(a2, w.z, accA3); accA3 = fmaf(a3, w.w, accA3);
                w = *reinterpret_cast<const float4*>(W0B + kc + k);
                accB0 = fmaf(a0, w.x, accB0); accB0 = fmaf(a1, w.y, accB0);
                accB0 = fmaf(a2, w.z, accB0); accB0 = fmaf(a3, w.w, accB0);
                w = *reinterpret_cast<const float4*>(W1B + kc + k);
                accB1 = fmaf(a0, w.x, accB1); accB1 = fmaf(a1, w.y, accB1);
                accB1 = fmaf(a2, w.z, accB1); accB1 = fmaf(a3, w.w, accB1);
                w = *reinterpret_cast<const float4*>(W2B + kc + k);
                accB2 = fmaf(a0, w.x, accB2); accB2 = fmaf(a1, w.y, accB2);
                accB2 = fmaf(a2, w.z, accB2); accB2 = fmaf(a3, w.w, accB2);
                w = *reinterpret_cast<const float4*>(W3B + kc + k);
                accB3 = fmaf(a0, w.x, accB3); accB3 = fmaf(a1, w.y, accB3);
                accB3 = fmaf(a2, w.z, accB3); accB3 = fmaf(a3, w.w, accB3);
            }
            __syncthreads();
        }
    }
    const int b = r0 + lane;
    lstm_out(accA0, accA1, accA2, accA3, b, jA, bih, bhh, hn, outp, tail, t);
    lstm_out(accB0, accB1, accB2, accB3, b, jB, bih, bhh, hn, outp, tail, t);
}

// One-time (per launch) precompute of Q = QL@QR, R = RL@RR; zero h0, c0.
__device__ void precompute(const float* QL, const float* QR,
                           const float* RL, const float* RR) {
    const int tid = (int)blockIdx.x * NT + (int)threadIdx.x;
    const int stride = GRID_BLOCKS * NT;
    for (int e = tid; e < NQP * HID * HID; e += stride) {
        int i = e >> 18;
        int rem = e & ((1 << 18) - 1);
        int m = rem >> 9, n = rem & 511;
        const float* L  = QL + i * HID * K_RANK + m * K_RANK;
        const float* Rp = QR + i * K_RANK * HID + n;
        float acc = 0.f;
#pragma unroll 8
        for (int k = 0; k < K_RANK; k++) acc = fmaf(L[k], Rp[k * HID], acc);
        g_Q[e] = acc;                    // [i][m][n]
    }
    for (int e = tid; e < NQP * HID * HID; e += stride) {
        int i = e >> 18;
        int rem = e & ((1 << 18) - 1);
        int n = rem >> 9, m = rem & 511;
        const float* L  = RL + i * HID * K_RANK + n * K_RANK;
        const float* Rp = RR + i * K_RANK * HID + m;
        float acc = 0.f;
#pragma unroll 8
        for (int k = 0; k < K_RANK; k++) acc = fmaf(L[k], Rp[k * HID], acc);
        g_R[e] = acc;                    // [i][n][m]
    }
    for (int e = tid; e < B_DIM * HID; e += stride) {
        g_h[0][e] = 0.f;
        g_c[e]    = 0.f;
    }
}

extern "C" __global__ void __launch_bounds__(NT, 1)
mogrifier_main(const float* __restrict__ x,
               const float* __restrict__ QL, const float* __restrict__ QR,
               const float* __restrict__ RL, const float* __restrict__ RR,
               const float* __restrict__ Wih, const float* __restrict__ Whh,
               const float* __restrict__ bih, const float* __restrict__ bhh,
               float* __restrict__ out) {
    __shared__ float As[CHUNK * PITCH];
    unsigned int epoch = 0;

    precompute(QL, QR, RL, RR);
    grid_barrier(epoch);

    float* tail = out + (size_t)S_LEN * B_DIM * HID;

    for (int t = 0; t < S_LEN; t++) {
        float* hc = g_h[t & 1];
        float* hn = g_h[(t + 1) & 1];
        const float* xt = x + (size_t)t * B_DIM * HID;

        mog_phase(As, hc,   g_Q,             xt,   g_xx);  grid_barrier(epoch);
        mog_phase(As, g_xx, g_R,             hc,   hc);    grid_barrier(epoch);
        mog_phase(As, hc,   g_Q + HID * HID, g_xx, g_xx);  grid_barrier(epoch);
        mog_phase(As, g_xx, g_R + HID * HID, hc,   hc);    grid_barrier(epoch);
        gates_phase(As, g_xx, hc, Wih, Whh, bih, bhh, hn,
                    out + (size_t)t * B_DIM * HID, tail, t);
        grid_barrier(epoch);
    }
}

extern "C" void kernel_launch(void* const* d_in, const int* in_sizes, int n_in,
                              void* d_out, int out_size) {
    const float* x   = (const float*)d_in[0];
    const float* QL  = (const float*)d_in[1];
    const float* QR  = (const float*)d_in[2];
    const float* RL  = (const float*)d_in[3];
    const float* RR  = (const float*)d_in[4];
    const float* Wih = (const float*)d_in[5];
    const float* Whh = (const float*)d_in[6];
    const float* bih = (const float*)d_in[7];
    const float* bhh = (const float*)d_in[8];
    (void)in_sizes; (void)n_in; (void)out_size;

    mg_init<<<1, 1>>>();
    mogrifier_main<<<GRID_BLOCKS, NT>>>(x, QL, QR, RL, RR, Wih, Whh,
                                        bih, bhh, (float*)d_out);
}

// round 5
// speedup vs baseline: 1.3696x; 1.3696x over previous
#include <cuda_runtime.h>

// ---------------------------------------------------------------------------
// MogrifierRNN persistent kernel, round 4.
//   - no-IVALL grid barrier (red.release / ld.acquire), L1 stays warm
//   - cross-SM activations via __ldcv/__stcg (L1-bypass => no staleness)
//   - full-A tile staged to smem once per phase (pitch 516, conflict-free LDS.128)
//   - W_hh slice resident in smem for the whole kernel (gates src1 = pure LDS)
// ---------------------------------------------------------------------------

#define S_LEN 512
#define B_DIM 128
#define HID   512
#define K_RANK 256
#define NQP   2

#define GRID_BLOCKS 128
#define NT          256
#define APITCH      516          // floats per staged A row (2064 B = 16 mod 128)

#define AS_FLOATS   (32 * APITCH)       // 16512
#define WH_FLOATS   (64 * HID)          // 32768
#define SMEM_BYTES  ((AS_FLOATS + WH_FLOATS) * 4)   // 197,120 B

// ------------------------- device scratch ----------------------------------
__device__ float g_Q[NQP * HID * HID];   // Q[i][m][n]
__device__ float g_R[NQP * HID * HID];   // R[i][n][m]
__device__ float g_xx[B_DIM * HID];
__device__ float g_h[2][B_DIM * HID];
__device__ float g_c[B_DIM * HID];
__device__ unsigned int g_bar;

__global__ void mg_init() { g_bar = 0u; }

__device__ __forceinline__ float sigf(float v) {
    return 1.0f / (1.0f + __expf(-v));
}

// Grid barrier WITHOUT gpu-scope fence lowering (no CCTL.IVALL => L1 survives).
// release-atomic orders this thread's prior (weak) stores; __syncthreads before
// it chains the whole block. Cross-SM consumers read with .cv, so no stale L1.
__device__ __forceinline__ void grid_barrier(unsigned int& epoch) {
    epoch += GRID_BLOCKS;
    __syncthreads();
    if (threadIdx.x == 0) {
        asm volatile("red.release.gpu.global.add.u32 [%0], %1;"
                     :: "l"(&g_bar), "r"(1u) : "memory");
        unsigned int v;
        do {
            asm volatile("ld.acquire.gpu.global.u32 %0, [%1];"
                         : "=r"(v) : "l"(&g_bar) : "memory");
        } while (v < epoch);
    }
    __syncthreads();
}

// Stage full A tile (32 rows x 512) into smem, L1-bypass reads.
// Layout As[row*APITCH + k]; global read + smem store both coalesced.
__device__ __forceinline__ void stage_A(float* As, const float* A, int r0) {
#pragma unroll
    for (int i = 0; i < 16; i++) {
        int e   = i * NT + (int)threadIdx.x;   // 0..4095 float4 slots
        int row = e >> 7;                       // 128 float4 per row
        int q   = e & 127;
        float4 v = __ldcv(reinterpret_cast<const float4*>(A + (r0 + row) * HID) + q);
        *reinterpret_cast<float4*>(As + row * APITCH + q * 4) = v;
    }
}

// Mogrifier phase: Out[b,j] = 2*sig(sum_k A[b,k] W[j,k]) * Mul[b,j]
// Tile 32 rows x 16 cols; thread = 1 row (lane) x 2 cols.
__device__ __forceinline__ void mog_phase(float* As, const float* Aglob,
                                          const float* __restrict__ W,
                                          const float* Mul, float* Out,
                                          int r0, int jA, int jB, int lane) {
    stage_A(As, Aglob, r0);
    const int b = r0 + lane;
    float m0 = __ldcv(Mul + b * HID + jA);     // prefetch, hides under GEMM
    float m1 = __ldcv(Mul + b * HID + jB);
    __syncthreads();

    const float4* __restrict__ WA = reinterpret_cast<const float4*>(W + jA * HID);
    const float4* __restrict__ WB = reinterpret_cast<const float4*>(W + jB * HID);
    const float4* Ar = reinterpret_cast<const float4*>(As + lane * APITCH);

    float acc0 = 0.f, acc1 = 0.f;
#pragma unroll 8
    for (int k4 = 0; k4 < HID / 4; k4++) {
        float4 a  = Ar[k4];
        float4 w0 = WA[k4];
        float4 w1 = WB[k4];
        acc0 = fmaf(a.x, w0.x, acc0); acc0 = fmaf(a.y, w0.y, acc0);
        acc0 = fmaf(a.z, w0.z, acc0); acc0 = fmaf(a.w, w0.w, acc0);
        acc1 = fmaf(a.x, w1.x, acc1); acc1 = fmaf(a.y, w1.y, acc1);
        acc1 = fmaf(a.z, w1.z, acc1); acc1 = fmaf(a.w, w1.w, acc1);
    }
    __stcg(Out + b * HID + jA, 2.0f * sigf(acc0) * m0);
    __stcg(Out + b * HID + jB, 2.0f * sigf(acc1) * m1);
}

// Gates + LSTM pointwise. src0: xx @ Wih^T (uniform LDG, L2); src1: h @ Whh^T
// (smem-resident slice). Thread: 1 row x 2 n-cols x 4 gates = 8 accumulators.
__device__ __forceinline__ void gates_phase(float* As, const float* Wh,
                                            const float* __restrict__ Wih,
                                            const float* __restrict__ bih,
                                            const float* __restrict__ bhh,
                                            const float* hcur, float* hn,
                                            float* outp, float* tail,
                                            int r0, int j0, int jA, int jB,
                                            int lane, int t) {
    stage_A(As, g_xx, r0);
    const int b = r0 + lane;
    float cA = g_c[b * HID + jA];              // block-private, prefetch
    float cB = g_c[b * HID + jB];
    float acc[8];
#pragma unroll
    for (int s = 0; s < 8; s++) acc[s] = 0.f;
    __syncthreads();

    const float4* Ar = reinterpret_cast<const float4*>(As + lane * APITCH);

    {   // ---- src0: xx @ Wih^T (weights via uniform LDG from L2) ----
        const float4* __restrict__ Wp[8];
#pragma unroll
        for (int g = 0; g < 4; g++) {
            Wp[2 * g]     = reinterpret_cast<const float4*>(Wih + (g * HID + jA) * HID);
            Wp[2 * g + 1] = reinterpret_cast<const float4*>(Wih + (g * HID + jB) * HID);
        }
#pragma unroll 2
        for (int k4 = 0; k4 < HID / 4; k4++) {
            float4 a = Ar[k4];
#pragma unroll
            for (int s = 0; s < 8; s++) {
                float4 w = Wp[s][k4];
                acc[s] = fmaf(a.x, w.x, acc[s]); acc[s] = fmaf(a.y, w.y, acc[s]);
                acc[s] = fmaf(a.z, w.z, acc[s]); acc[s] = fmaf(a.w, w.w, acc[s]);
            }
        }
    }
    __syncthreads();
    stage_A(As, hcur, r0);
    __syncthreads();
    {   // ---- src1: h @ Whh^T (weights resident in smem) ----
        const float4* Whp[8];
#pragma unroll
        for (int g = 0; g < 4; g++) {
            Whp[2 * g]     = reinterpret_cast<const float4*>(Wh + (g * 16 + (jA - j0)) * HID);
            Whp[2 * g + 1] = reinterpret_cast<const float4*>(Wh + (g * 16 + (jB - j0)) * HID);
        }
#pragma unroll 2
        for (int k4 = 0; k4 < HID / 4; k4++) {
            float4 a = Ar[k4];
#pragma unroll
            for (int s = 0; s < 8; s++) {
                float4 w = Whp[s][k4];
                acc[s] = fmaf(a.x, w.x, acc[s]); acc[s] = fmaf(a.y, w.y, acc[s]);
                acc[s] = fmaf(a.z, w.z, acc[s]); acc[s] = fmaf(a.w, w.w, acc[s]);
            }
        }
    }

    // ---- LSTM pointwise ----
    float iA = acc[0] + bih[jA]        + bhh[jA];
    float fA = acc[2] + bih[512 + jA]  + bhh[512 + jA];
    float gA = acc[4] + bih[1024 + jA] + bhh[1024 + jA];
    float oA = acc[6] + bih[1536 + jA] + bhh[1536 + jA];
    float iB = acc[1] + bih[jB]        + bhh[jB];
    float fB = acc[3] + bih[512 + jB]  + bhh[512 + jB];
    float gB = acc[5] + bih[1024 + jB] + bhh[1024 + jB];
    float oB = acc[7] + bih[1536 + jB] + bhh[1536 + jB];

    float cnA = sigf(fA) * cA + sigf(iA) * tanhf(gA);
    float hA  = sigf(oA) * tanhf(cnA);
    float cnB = sigf(fB) * cB + sigf(iB) * tanhf(gB);
    float hB  = sigf(oB) * tanhf(cnB);

    int idxA = b * HID + jA, idxB = b * HID + jB;
    g_c[idxA] = cnA;  g_c[idxB] = cnB;
    __stcg(hn + idxA, hA);  __stcg(hn + idxB, hB);
    outp[idxA] = hA;  outp[idxB] = hB;
    if (t == S_LEN - 1) {
        tail[idxA] = hA;  tail[B_DIM * HID + idxA] = cnA;
        tail[idxB] = hB;  tail[B_DIM * HID + idxB] = cnB;
    }
}

// One-time precompute of Q = QL@QR, R = RL@RR; zero h0, c0.
__device__ void precompute(const float* QL, const float* QR,
                           const float* RL, const float* RR) {
    const int tid = (int)blockIdx.x * NT + (int)threadIdx.x;
    const int stride = GRID_BLOCKS * NT;
    for (int e = tid; e < NQP * HID * HID; e += stride) {
        int i = e >> 18;
        int rem = e & ((1 << 18) - 1);
        int m = rem >> 9, n = rem & 511;
        const float* L  = QL + i * HID * K_RANK + m * K_RANK;
        const float* Rp = QR + i * K_RANK * HID + n;
        float acc = 0.f;
#pragma unroll 8
        for (int k = 0; k < K_RANK; k++) acc = fmaf(L[k], Rp[k * HID], acc);
        g_Q[e] = acc;
    }
    for (int e = tid; e < NQP * HID * HID; e += stride) {
        int i = e >> 18;
        int rem = e & ((1 << 18) - 1);
        int n = rem >> 9, m = rem & 511;
        const float* L  = RL + i * HID * K_RANK + n * K_RANK;
        const float* Rp = RR + i * K_RANK * HID + m;
        float acc = 0.f;
#pragma unroll 8
        for (int k = 0; k < K_RANK; k++) acc = fmaf(L[k], Rp[k * HID], acc);
        g_R[e] = acc;
    }
    for (int e = tid; e < B_DIM * HID; e += stride) {
        g_h[0][e] = 0.f;
        g_c[e]    = 0.f;
    }
}

extern "C" __global__ void __launch_bounds__(NT, 1)
mogrifier_main(const float* __restrict__ x,
               const float* __restrict__ QL, const float* __restrict__ QR,
               const float* __restrict__ RL, const float* __restrict__ RR,
               const float* __restrict__ Wih, const float* __restrict__ Whh,
               const float* __restrict__ bih, const float* __restrict__ bhh,
               float* __restrict__ out) {
    extern __shared__ float smem[];
    float* As = smem;
    float* Wh = smem + AS_FLOATS;

    const int lane = threadIdx.x & 31, wp = (int)threadIdx.x >> 5;
    const int rt = blockIdx.x & 3, ct = (int)blockIdx.x >> 2;
    const int r0 = rt * 32, j0 = ct * 16;
    const int jA = j0 + 2 * wp, jB = jA + 1;
    unsigned int epoch = 0;

    precompute(QL, QR, RL, RR);

    // Stage this block's Whh slice (64 gate-rows x 512) into smem, once.
#pragma unroll
    for (int i = 0; i < 32; i++) {
        int e = i * NT + (int)threadIdx.x;   // 0..8191 float4
        int rowIdx = e >> 7, q = e & 127;
        int g = rowIdx >> 4, cc = rowIdx & 15;
        float4 v = *(reinterpret_cast<const float4*>(Whh + (g * HID + j0 + cc) * HID) + q);
        *reinterpret_cast<float4*>(Wh + rowIdx * HID + q * 4) = v;
    }

    grid_barrier(epoch);

    float* tail = out + (size_t)S_LEN * B_DIM * HID;

    for (int t = 0; t < S_LEN; t++) {
        float* hc = g_h[t & 1];
        float* hn = g_h[(t + 1) & 1];
        const float* xt = x + (size_t)t * B_DIM * HID;

        mog_phase(As, hc,   g_Q,             xt,   g_xx, r0, jA, jB, lane);
        grid_barrier(epoch);
        mog_phase(As, g_xx, g_R,             hc,   hc,   r0, jA, jB, lane);
        grid_barrier(epoch);
        mog_phase(As, hc,   g_Q + HID * HID, g_xx, g_xx, r0, jA, jB, lane);
        grid_barrier(epoch);
        mog_phase(As, g_xx, g_R + HID * HID, hc,   hc,   r0, jA, jB, lane);
        grid_barrier(epoch);
        gates_phase(As, Wh, Wih, bih, bhh, hc, hn,
                    out + (size_t)t * B_DIM * HID, tail,
                    r0, j0, jA, jB, lane, t);
        grid_barrier(epoch);
    }
}

extern "C" void kernel_launch(void* const* d_in, const int* in_sizes, int n_in,
                              void* d_out, int out_size) {
    const float* x   = (const float*)d_in[0];
    const float* QL  = (const float*)d_in[1];
    const float* QR  = (const float*)d_in[2];
    const float* RL  = (const float*)d_in[3];
    const float* RR  = (const float*)d_in[4];
    const float* Wih = (const float*)d_in[5];
    const float* Whh = (const float*)d_in[6];
    const float* bih = (const float*)d_in[7];
    const float* bhh = (const float*)d_in[8];
    (void)in_sizes; (void)n_in; (void)out_size;

    cudaFuncSetAttribute(mogrifier_main,
                         cudaFuncAttributeMaxDynamicSharedMemorySize, SMEM_BYTES);

    mg_init<<<1, 1>>>();
    mogrifier_main<<<GRID_BLOCKS, NT, SMEM_BYTES>>>(x, QL, QR, RL, RR,
                                                    Wih, Whh, bih, bhh,
                                                    (float*)d_out);
}